// round 9
// baseline (speedup 1.0000x reference)
#include <cuda_runtime.h>
#include <cuda_fp16.h>
#include <math.h>

// Problem constants (fixed by the reference)
#define NV 100000
#define NB 8
#define TILE_V 128
#define NTILES ((NV + TILE_V - 1) / TILE_V)   // 782
#define NBLK 592                               // prep grid: 148 SMs x 4
#define TBLK 432                               // transpose blocks in prep
#define CBLK (NBLK - TBLK)                     // compact blocks in prep (160)
#define CHUNK 2048
#define EMAX 1200064
#define EBLK (148 * 6)                         // edge grid
#define EWARPS (EBLK * 8)
#define PERMAX 96                              // >= ceil((EMAX/2)/EWARPS)

// Scratch: 16B fp16 record per (v,b): half2{x0,x1}, half2{x2,dx0}, half2{dx1,dx2}, pad.
// One vertex = 8 records = 128B line. Total 12.8 MB (L2-resident).
__device__ uint4 g_v[(size_t)NV * NB];
__device__ int2 g_edges[EMAX / 2 + 128];
__device__ int g_ecount;                 // zero-init; reset by edge kernel's final block
__device__ double g_acc[NB];             // zero-init; reset by edge kernel's final block
__device__ unsigned g_done;              // zero-init; reset by edge kernel's final block

// ---------------------------------------------------------------------------
// Kernel A: transpose (blocks [0,TBLK)) overlapped with s<d edge compaction
// (blocks [TBLK,NBLK)). Kernel boundary is the phase barrier.
// ---------------------------------------------------------------------------
__global__ void __launch_bounds__(256, 4)
prep_kernel(const float* __restrict__ dx, const float* __restrict__ x,
            const int* __restrict__ es, const int* __restrict__ ed, int E) {
    __shared__ float4 sx4[NB][TILE_V * 3 / 4 + 1];   // [8][97]
    __shared__ float4 sdx4[NB][TILE_V * 3 / 4 + 1];
    __shared__ int wsum[8];
    __shared__ int sbase;

    const int tid  = threadIdx.x;
    const int bid  = blockIdx.x;
    const int lane = tid & 31;
    const int warp = tid >> 5;

    if (bid < TBLK) {
        for (int t = bid; t < NTILES; t += TBLK) {
            const int v0 = t * TILE_V;
            const int nv = min(TILE_V, NV - v0);
            const int nf4 = nv * 3 / 4;
            #pragma unroll
            for (int k = 0; k < 3; k++) {
                int i = k * 256 + tid;                // [0, 768)
                int b = i / 96;
                int j = i - b * 96;
                size_t g4 = (size_t)b * (NV * 3 / 4) + (size_t)v0 * 3 / 4 + j;
                if (j < nf4) {
                    sx4[b][j]  = ((const float4*)x)[g4];
                    sdx4[b][j] = ((const float4*)dx)[g4];
                }
            }
            __syncthreads();
            const float* sxf  = (const float*)sx4;
            const float* sdxf = (const float*)sdx4;
            const int ROWF = (TILE_V * 3 / 4 + 1) * 4;
            uint4* outp = g_v + (size_t)v0 * NB;
            #pragma unroll
            for (int k = 0; k < 4; k++) {
                int rec = k * 256 + tid;              // [0, 1024)
                int v = rec >> 3;
                int b = rec & (NB - 1);
                if (v < nv) {
                    int j = b * ROWF + v * 3;
                    __half2 h0 = __floats2half2_rn(sxf[j],      sxf[j + 1]);
                    __half2 h1 = __floats2half2_rn(sxf[j + 2],  sdxf[j]);
                    __half2 h2 = __floats2half2_rn(sdxf[j + 1], sdxf[j + 2]);
                    uint4 r;
                    r.x = *(unsigned int*)&h0;
                    r.y = *(unsigned int*)&h1;
                    r.z = *(unsigned int*)&h2;
                    r.w = 0u;
                    outp[rec] = r;
                }
            }
            __syncthreads();
        }
    } else {
        const int cid = bid - TBLK;
        const int nchunks = (E + CHUNK - 1) / CHUNK;
        for (int c = cid; c < nchunks; c += CBLK) {
            const int base = c * CHUNK;
            int s[8], d[8];
            bool f[8];
            int cnt = 0;
            #pragma unroll
            for (int k = 0; k < 8; k++) {
                int e = base + k * 256 + tid;
                bool fl = false; int ss = 0, dd = 0;
                if (e < E) { ss = es[e]; dd = ed[e]; fl = ss < dd; }
                s[k] = ss; d[k] = dd; f[k] = fl; cnt += fl;
            }
            int inc = cnt;
            #pragma unroll
            for (int o = 1; o < 32; o <<= 1) {
                int t2 = __shfl_up_sync(0xffffffffu, inc, o);
                if (lane >= o) inc += t2;
            }
            if (lane == 31) wsum[warp] = inc;
            __syncthreads();
            if (tid == 0) {
                int tot = 0;
                #pragma unroll
                for (int w = 0; w < 8; w++) { int t2 = wsum[w]; wsum[w] = tot; tot += t2; }
                sbase = atomicAdd(&g_ecount, tot);
            }
            __syncthreads();
            int pos = sbase + wsum[warp] + (inc - cnt);
            #pragma unroll
            for (int k = 0; k < 8; k++)
                if (f[k]) g_edges[pos++] = make_int2(s[k], d[k]);
            __syncthreads();
        }
    }
}

// ---------------------------------------------------------------------------
// Kernel B: edge gather + reduce + finalize.
// Per-warp contiguous edge range is staged into SMEM first, so the gather
// loop's addresses come from LDS (29 cyc) instead of a dependent LDG chain.
// x4-unrolled body: 8 independent LDG.128 gathers in flight per iteration.
// ---------------------------------------------------------------------------
__device__ __forceinline__ float edge_term(uint4 rs, uint4 rd) {
    __half2 e0 = __hsub2(*(__half2*)&rd.x, *(__half2*)&rs.x);
    __half2 e1 = __hsub2(*(__half2*)&rd.y, *(__half2*)&rs.y);
    __half2 e2 = __hsub2(*(__half2*)&rd.z, *(__half2*)&rs.z);
    float2 f0 = __half22float2(e0);
    float2 f1 = __half22float2(e1);
    float2 f2 = __half22float2(e2);
    float diffx = f0.x * f0.x + f0.y * f0.y + f1.x * f1.x;
    float diffd = f1.y * f1.y + f2.x * f2.x + f2.y * f2.y;
    return fabsf(diffx - diffd);
}

__global__ void __launch_bounds__(256, 4)
edge_kernel(float* __restrict__ out, int E) {
    __shared__ int2 sedges[8][PERMAX];     // per-warp staged edge indices (6 KB)
    __shared__ float sacc[8][9];
    __shared__ bool slast;

    const int tid  = threadIdx.x;
    const int lane = tid & 31;
    const int warp = tid >> 5;
    const int b    = lane & 7;
    const int grp  = lane >> 3;
    const int gwarp = blockIdx.x * 8 + warp;

    const int EC  = *(volatile int*)&g_ecount;
    const int per = (EC + EWARPS - 1) / EWARPS;    // ~85 contiguous edges per warp
    const int start = min(gwarp * per, EC);
    const int cnt   = min(per, EC - start);

    // Stage this warp's index range into SMEM (coalesced int2 loads).
    for (int i = lane; i < cnt; i += 32)
        sedges[warp][i] = g_edges[start + i];
    __syncwarp();

    float acc = 0.f;
    int k = grp;
    // Steady state: 16 edges per warp-iteration, 4 per lane-group.
    // All 8 gather LDG.128s are independent (addresses from LDS).
    for (; k + 12 < cnt; k += 16) {
        int2 sd0 = sedges[warp][k];
        int2 sd1 = sedges[warp][k + 4];
        int2 sd2 = sedges[warp][k + 8];
        int2 sd3 = sedges[warp][k + 12];
        uint4 a0 = g_v[(unsigned)sd0.x * NB + b];
        uint4 c0 = g_v[(unsigned)sd0.y * NB + b];
        uint4 a1 = g_v[(unsigned)sd1.x * NB + b];
        uint4 c1 = g_v[(unsigned)sd1.y * NB + b];
        uint4 a2 = g_v[(unsigned)sd2.x * NB + b];
        uint4 c2 = g_v[(unsigned)sd2.y * NB + b];
        uint4 a3 = g_v[(unsigned)sd3.x * NB + b];
        uint4 c3 = g_v[(unsigned)sd3.y * NB + b];
        acc += edge_term(a0, c0);
        acc += edge_term(a1, c1);
        acc += edge_term(a2, c2);
        acc += edge_term(a3, c3);
    }
    for (; k < cnt; k += 4) {
        int2 sd = sedges[warp][k];
        uint4 rs = g_v[(unsigned)sd.x * NB + b];
        uint4 rd = g_v[(unsigned)sd.y * NB + b];
        acc += edge_term(rs, rd);
    }

    acc += __shfl_xor_sync(0xffffffff, acc, 8);
    acc += __shfl_xor_sync(0xffffffff, acc, 16);

    if (lane < 8) sacc[warp][b] = acc;
    __syncthreads();
    if (warp == 0 && lane < 8) {
        float s = 0.f;
        #pragma unroll
        for (int w = 0; w < 8; w++) s += sacc[w][lane];
        atomicAdd(&g_acc[lane], (double)s);
    }
    __syncthreads();

    // last-block finalize + state reset (keeps launches deterministic)
    if (tid == 0) {
        __threadfence();
        slast = (atomicAdd(&g_done, 1u) == EBLK - 1);
    }
    __syncthreads();
    if (slast) {
        if (tid < NB) {
            double a = *(volatile double*)&g_acc[tid];
            out[tid] = (float)(2.0 * a / (double)E);
            g_acc[tid] = 0.0;
        }
        if (tid == NB) g_ecount = 0;
        if (tid == NB + 1) g_done = 0;
    }
}

extern "C" void kernel_launch(void* const* d_in, const int* in_sizes, int n_in,
                              void* d_out, int out_size) {
    // metadata order: dx, x, edge_src, edge_dst
    const float* dx = (const float*)d_in[0];
    const float* x  = (const float*)d_in[1];
    const int* es   = (const int*)d_in[2];
    const int* ed   = (const int*)d_in[3];
    float* out      = (float*)d_out;
    const int E     = in_sizes[2];

    prep_kernel<<<NBLK, 256>>>(dx, x, es, ed, E);
    edge_kernel<<<EBLK, 256>>>(out, E);
}